// round 2
// baseline (speedup 1.0000x reference)
#include <cuda_runtime.h>
#include <cuda_bf16.h>
#include <math.h>

// ---------------- Model constants ----------------
#define LNUM 8
#define H    1024
#define NH   16
#define NKV  8
#define HD   128
#define IDIM 3072
#define VOC  32000
#define BATCH 2
#define SEQ  1024
#define TOK  (BATCH*SEQ)          // 2048
#define QD   (NH*HD)              // 2048
#define KVD  (NKV*HD)             // 1024
#define EPS  1e-6f

// ---------------- Scratch (device globals; no allocation allowed) ----------------
__device__ float g_h  [(size_t)TOK * H];
__device__ float g_x  [(size_t)TOK * H];
__device__ float g_q  [(size_t)TOK * QD];
__device__ float g_k  [(size_t)TOK * KVD];
__device__ float g_v  [(size_t)TOK * KVD];
__device__ float g_ctx[(size_t)TOK * QD];
__device__ float g_mg [(size_t)TOK * IDIM];
__device__ float g_mu [(size_t)TOK * IDIM];
__device__ float g_cos[(size_t)SEQ * 64];
__device__ float g_sin[(size_t)SEQ * 64];

// ---------------- RoPE tables (double-precision trig of fp32-rounded angle) -------
__global__ void rope_table_kernel(float* __restrict__ cost, float* __restrict__ sint) {
    int pos = blockIdx.x;      // 0..SEQ-1
    int i   = threadIdx.x;     // 0..63
    float invf = (float)pow(1000000.0, -(double)i / 64.0);
    float angf = (float)pos * invf;          // fp32 product, like the reference
    double ang = (double)angf;
    cost[pos * 64 + i] = (float)cos(ang);
    sint[pos * 64 + i] = (float)sin(ang);
}

// ---------------- Embedding gather ----------------
__global__ void embed_kernel(const int* __restrict__ ids,
                             const float* __restrict__ emb,
                             float* __restrict__ out) {
    int t = blockIdx.x;
    int id = ids[t];
    const float* src = emb + (size_t)id * H;
    float* dst = out + (size_t)t * H;
    for (int i = threadIdx.x; i < H; i += blockDim.x) dst[i] = src[i];
}

// ---------------- Row RMSNorm (width W, one 256-thread block per row) ----------------
__global__ void rmsnorm_kernel(const float* __restrict__ in,
                               const float* __restrict__ w,
                               float* __restrict__ out, int W) {
    __shared__ float red[256];
    int row = blockIdx.x;
    const float* x = in + (size_t)row * W;
    float s = 0.f;
    for (int i = threadIdx.x; i < W; i += 256) { float v = x[i]; s += v * v; }
    red[threadIdx.x] = s;
    __syncthreads();
    for (int st = 128; st > 0; st >>= 1) {
        if (threadIdx.x < st) red[threadIdx.x] += red[threadIdx.x + st];
        __syncthreads();
    }
    float rms = rsqrtf(red[0] / (float)W + EPS);
    float* o = out + (size_t)row * W;
    for (int i = threadIdx.x; i < W; i += 256) o[i] = x[i] * rms * w[i];
}

// ---------------- Per-head RMSNorm + RoPE (128 threads per (token, head)) ----------------
__global__ void qk_norm_rope_kernel(float* __restrict__ x,
                                    const float* __restrict__ w,
                                    const float* __restrict__ cost,
                                    const float* __restrict__ sint,
                                    int nheads) {
    __shared__ float sh[HD];
    __shared__ float red[HD];
    int t  = blockIdx.x / nheads;
    int hh = blockIdx.x % nheads;
    int pos = t % SEQ;
    float* p = x + ((size_t)t * nheads + hh) * HD;
    int d = threadIdx.x;
    float v = p[d];
    red[d] = v * v;
    __syncthreads();
    for (int st = 64; st > 0; st >>= 1) {
        if (d < st) red[d] += red[d + st];
        __syncthreads();
    }
    float rms = rsqrtf(red[0] / (float)HD + EPS);
    float xn = v * rms * w[d];
    sh[d] = xn;
    __syncthreads();
    int fi = d & 63;
    float c = cost[pos * 64 + fi];
    float s = sint[pos * 64 + fi];
    float other = (d < 64) ? -sh[d + 64] : sh[d - 64];
    p[d] = xn * c + other * s;
}

// ---------------- Simple tiled FP32 GEMM: C = A[MxK] @ B[KxN], optional accumulate ------
// 32x32 tile, BK=32, 256 threads, each thread computes 4 rows x 1 col.
__global__ void gemm32_kernel(const float* __restrict__ A,
                              const float* __restrict__ B,
                              float* __restrict__ C,
                              int M, int N, int K, int accum) {
    __shared__ float As[32][33];
    __shared__ float Bs[32][33];
    int tid = threadIdx.x;
    int tx = tid & 31;        // col within tile
    int ty = tid >> 5;        // 0..7
    int brow = blockIdx.y * 32, bcol = blockIdx.x * 32;

    float acc[4] = {0.f, 0.f, 0.f, 0.f};

    for (int k0 = 0; k0 < K; k0 += 32) {
        for (int idx = tid; idx < 32 * 32; idx += 256) {
            int r = idx >> 5, c = idx & 31;
            As[r][c] = A[(size_t)(brow + r) * K + k0 + c];
            Bs[r][c] = B[(size_t)(k0 + r) * N + bcol + c];
        }
        __syncthreads();
#pragma unroll 8
        for (int kk = 0; kk < 32; kk++) {
            float bv = Bs[kk][tx];
#pragma unroll
            for (int i = 0; i < 4; i++)
                acc[i] += As[ty + 8 * i][kk] * bv;
        }
        __syncthreads();
    }

#pragma unroll
    for (int i = 0; i < 4; i++) {
        size_t ci = (size_t)(brow + ty + 8 * i) * N + bcol + tx;
        if (accum) C[ci] += acc[i];
        else       C[ci]  = acc[i];
    }
}

// ---------------- Attention: block per (b, h, q), two-pass softmax -------------------
__global__ void attn2_kernel(const float* __restrict__ q,
                             const float* __restrict__ k,
                             const float* __restrict__ v,
                             float* __restrict__ ctx) {
    __shared__ float sc[SEQ];       // scores / probs
    __shared__ float qsh[HD];
    __shared__ float red[HD];
    int gid = blockIdx.x;           // b*NH*SEQ + hh*SEQ + qs
    int qs = gid % SEQ;
    int hh = (gid / SEQ) % NH;
    int b  = gid / (SEQ * NH);
    int tid = threadIdx.x;          // 128

    const float* qr = q + ((size_t)(b * SEQ + qs) * NH + hh) * HD;
    int kvh = hh >> 1;              // rep = NH/NKV = 2 (jnp.repeat semantics)
    const float* kb = k + (size_t)b * SEQ * KVD + (size_t)kvh * HD;
    const float* vb = v + (size_t)b * SEQ * KVD + (size_t)kvh * HD;

    qsh[tid] = qr[tid];
    __syncthreads();

    const float scale = 0.08838834764831845f; // 1/sqrt(128)

    // Pass 1: scores + max
    float lmax = -1e30f;
    for (int j = tid; j <= qs; j += 128) {
        const float* kr = kb + (size_t)j * KVD;
        float s = 0.f;
#pragma unroll 8
        for (int d = 0; d < HD; d++) s += qsh[d] * kr[d];
        s *= scale;
        sc[j] = s;
        lmax = fmaxf(lmax, s);
    }
    red[tid] = lmax;
    __syncthreads();
    for (int st = 64; st > 0; st >>= 1) {
        if (tid < st) red[tid] = fmaxf(red[tid], red[tid + st]);
        __syncthreads();
    }
    float mx = red[0];
    __syncthreads();

    // Pass 2: exp + sum
    float lsum = 0.f;
    for (int j = tid; j <= qs; j += 128) {
        float p = expf(sc[j] - mx);
        sc[j] = p;
        lsum += p;
    }
    red[tid] = lsum;
    __syncthreads();
    for (int st = 64; st > 0; st >>= 1) {
        if (tid < st) red[tid] += red[tid + st];
        __syncthreads();
    }
    float inv = 1.f / red[0];
    __syncthreads();

    // Pass 3: weighted sum of v — thread owns head dim d = tid (coalesced v reads)
    float acc = 0.f;
    for (int j = 0; j <= qs; j++)
        acc += sc[j] * vb[(size_t)j * KVD + tid];

    ctx[((size_t)(b * SEQ + qs) * NH + hh) * HD + tid] = acc * inv;
}

// ---------------- SiLU(g) * u (in place into g) ----------------
__global__ void silu_mul_kernel(float* __restrict__ g, const float* __restrict__ u, size_t n) {
    size_t i = (size_t)blockIdx.x * blockDim.x + threadIdx.x;
    if (i < n) {
        float x = g[i];
        g[i] = (x / (1.f + expf(-x))) * u[i];
    }
}

// ---------------- Host orchestration ----------------
static void launch_gemm(const float* A, const float* B, float* C,
                        int M, int N, int K, int accum) {
    dim3 grid(N / 32, M / 32);
    gemm32_kernel<<<grid, 256>>>(A, B, C, M, N, K, accum);
}

extern "C" void kernel_launch(void* const* d_in, const int* in_sizes, int n_in,
                              void* d_out, int out_size) {
    const int*   input_ids = (const int*)  d_in[0];
    const float* embed     = (const float*)d_in[1];
    const float* Wq        = (const float*)d_in[2];
    const float* Wk        = (const float*)d_in[3];
    const float* Wv        = (const float*)d_in[4];
    const float* Wo        = (const float*)d_in[5];
    const float* qn        = (const float*)d_in[6];
    const float* kn        = (const float*)d_in[7];
    const float* ln1       = (const float*)d_in[8];
    const float* ln2       = (const float*)d_in[9];
    const float* Wg        = (const float*)d_in[10];
    const float* Wu        = (const float*)d_in[11];
    const float* Wd        = (const float*)d_in[12];
    const float* norm_w    = (const float*)d_in[13];
    const float* lm_head   = (const float*)d_in[14];
    float* out = (float*)d_out;

    float *h, *x, *q, *k, *v, *ctx, *mg, *mu, *cost, *sint;
    cudaGetSymbolAddress((void**)&h,    g_h);
    cudaGetSymbolAddress((void**)&x,    g_x);
    cudaGetSymbolAddress((void**)&q,    g_q);
    cudaGetSymbolAddress((void**)&k,    g_k);
    cudaGetSymbolAddress((void**)&v,    g_v);
    cudaGetSymbolAddress((void**)&ctx,  g_ctx);
    cudaGetSymbolAddress((void**)&mg,   g_mg);
    cudaGetSymbolAddress((void**)&mu,   g_mu);
    cudaGetSymbolAddress((void**)&cost, g_cos);
    cudaGetSymbolAddress((void**)&sint, g_sin);

    // RoPE tables + embedding
    rope_table_kernel<<<SEQ, 64>>>(cost, sint);
    embed_kernel<<<TOK, 256>>>(input_ids, embed, h);

    for (int l = 0; l < LNUM; l++) {
        const float* wq = Wq + (size_t)l * H * QD;
        const float* wk = Wk + (size_t)l * H * KVD;
        const float* wv = Wv + (size_t)l * H * KVD;
        const float* wo = Wo + (size_t)l * QD * H;
        const float* wg = Wg + (size_t)l * H * IDIM;
        const float* wu = Wu + (size_t)l * H * IDIM;
        const float* wd = Wd + (size_t)l * IDIM * H;

        // ---- Attention block ----
        rmsnorm_kernel<<<TOK, 256>>>(h, ln1 + (size_t)l * H, x, H);
        launch_gemm(x, wq, q, TOK, QD,  H, 0);
        launch_gemm(x, wk, k, TOK, KVD, H, 0);
        launch_gemm(x, wv, v, TOK, KVD, H, 0);
        qk_norm_rope_kernel<<<TOK * NH,  HD>>>(q, qn + (size_t)l * HD, cost, sint, NH);
        qk_norm_rope_kernel<<<TOK * NKV, HD>>>(k, kn + (size_t)l * HD, cost, sint, NKV);
        attn2_kernel<<<BATCH * NH * SEQ, 128>>>(q, k, v, ctx);
        launch_gemm(ctx, wo, h, TOK, H, QD, 1);   // h += ctx @ Wo

        // ---- MLP block ----
        rmsnorm_kernel<<<TOK, 256>>>(h, ln2 + (size_t)l * H, x, H);
        launch_gemm(x, wg, mg, TOK, IDIM, H, 0);
        launch_gemm(x, wu, mu, TOK, IDIM, H, 0);
        {
            size_t n = (size_t)TOK * IDIM;
            silu_mul_kernel<<<(unsigned)((n + 255) / 256), 256>>>(mg, mu, n);
        }
        launch_gemm(mg, wd, h, TOK, H, IDIM, 1);  // h += (silu(g)*u) @ Wd
    }

    // Final norm + LM head
    rmsnorm_kernel<<<TOK, 256>>>(h, norm_w, x, H);
    launch_gemm(x, lm_head, out, TOK, VOC, H, 0);
}

// round 3
// speedup vs baseline: 5.2564x; 5.2564x over previous
#include <cuda_runtime.h>
#include <cuda_bf16.h>
#include <math.h>

// ---------------- Model constants ----------------
#define LNUM 8
#define H    1024
#define NH   16
#define NKV  8
#define HD   128
#define IDIM 3072
#define VOC  32000
#define BATCH 2
#define SEQ  1024
#define TOK  (BATCH*SEQ)          // 2048
#define QD   (NH*HD)              // 2048
#define KVD  (NKV*HD)             // 1024
#define EPS  1e-6f

// ---------------- Scratch (device globals; no allocation allowed) ----------------
__device__ float g_h  [(size_t)TOK * H];
__device__ float g_x  [(size_t)TOK * H];
__device__ float g_q  [(size_t)TOK * QD];
__device__ float g_k  [(size_t)TOK * KVD];
__device__ float g_v  [(size_t)TOK * KVD];
__device__ float g_ctx[(size_t)TOK * QD];
__device__ float g_mg [(size_t)TOK * IDIM];
__device__ float g_mu [(size_t)TOK * IDIM];
__device__ float g_cos[(size_t)SEQ * 64];
__device__ float g_sin[(size_t)SEQ * 64];

// ---------------- RoPE tables (double-precision trig of fp32-rounded angle) -------
__global__ void rope_table_kernel(float* __restrict__ cost, float* __restrict__ sint) {
    int pos = blockIdx.x;      // 0..SEQ-1
    int i   = threadIdx.x;     // 0..63
    float invf = (float)pow(1000000.0, -(double)i / 64.0);
    float angf = (float)pos * invf;          // fp32 product, like the reference
    double ang = (double)angf;
    cost[pos * 64 + i] = (float)cos(ang);
    sint[pos * 64 + i] = (float)sin(ang);
}

// ---------------- Embedding gather ----------------
__global__ void embed_kernel(const int* __restrict__ ids,
                             const float* __restrict__ emb,
                             float* __restrict__ out) {
    int t = blockIdx.x;
    int id = ids[t];
    const float* src = emb + (size_t)id * H;
    float* dst = out + (size_t)t * H;
    for (int i = threadIdx.x; i < H; i += blockDim.x) dst[i] = src[i];
}

// ---------------- Row RMSNorm (width W, one 256-thread block per row) ----------------
__global__ void rmsnorm_kernel(const float* __restrict__ in,
                               const float* __restrict__ w,
                               float* __restrict__ out, int W) {
    __shared__ float red[256];
    int row = blockIdx.x;
    const float* x = in + (size_t)row * W;
    float s = 0.f;
    for (int i = threadIdx.x; i < W; i += 256) { float v = x[i]; s += v * v; }
    red[threadIdx.x] = s;
    __syncthreads();
    for (int st = 128; st > 0; st >>= 1) {
        if (threadIdx.x < st) red[threadIdx.x] += red[threadIdx.x + st];
        __syncthreads();
    }
    float rms = rsqrtf(red[0] / (float)W + EPS);
    float* o = out + (size_t)row * W;
    for (int i = threadIdx.x; i < W; i += 256) o[i] = x[i] * rms * w[i];
}

// ---------------- Per-head RMSNorm + RoPE (128 threads per (token, head)) ----------------
__global__ void qk_norm_rope_kernel(float* __restrict__ x,
                                    const float* __restrict__ w,
                                    const float* __restrict__ cost,
                                    const float* __restrict__ sint,
                                    int nheads) {
    __shared__ float sh[HD];
    __shared__ float red[HD];
    int t  = blockIdx.x / nheads;
    int hh = blockIdx.x % nheads;
    int pos = t % SEQ;
    float* p = x + ((size_t)t * nheads + hh) * HD;
    int d = threadIdx.x;
    float v = p[d];
    red[d] = v * v;
    __syncthreads();
    for (int st = 64; st > 0; st >>= 1) {
        if (d < st) red[d] += red[d + st];
        __syncthreads();
    }
    float rms = rsqrtf(red[0] / (float)HD + EPS);
    float xn = v * rms * w[d];
    sh[d] = xn;
    __syncthreads();
    int fi = d & 63;
    float c = cost[pos * 64 + fi];
    float s = sint[pos * 64 + fi];
    float other = (d < 64) ? -sh[d + 64] : sh[d - 64];
    p[d] = xn * c + other * s;
}

// ---------------- Fast FP32 GEMM: C = A[MxK] @ B[KxN], optional accumulate ------
// 128x128 tile, BK=16, 256 threads, 8x8 micro-tile, double-buffered SMEM.
// Requires M%128==0, N%128==0, K%16==0.
template <bool ACCUM>
__global__ __launch_bounds__(256) void sgemm128_kernel(const float* __restrict__ A,
                                                       const float* __restrict__ B,
                                                       float* __restrict__ C,
                                                       int M, int N, int K) {
    __shared__ float As[2][16][132];  // A^T tile (k, m), padded
    __shared__ float Bs[2][16][128];  // B tile (k, n)
    int tid = threadIdx.x;
    int brow = blockIdx.y * 128, bcol = blockIdx.x * 128;

    int ar = tid >> 2;             // 0..63 (A rows ar, ar+64)
    int ac = (tid & 3) << 2;       // 0,4,8,12
    int br = tid >> 5;             // 0..7  (B k-rows br, br+8)
    int bc = (tid & 31) << 2;      // 0..124
    int tx = tid & 15;             // micro col group
    int ty = tid >> 4;             // micro row group

    float4 a0, a1, b0, b1;

    // --- load tile 0 ---
    a0 = *(const float4*)&A[(size_t)(brow + ar)      * K + ac];
    a1 = *(const float4*)&A[(size_t)(brow + ar + 64) * K + ac];
    b0 = *(const float4*)&B[(size_t)(br)     * N + bcol + bc];
    b1 = *(const float4*)&B[(size_t)(br + 8) * N + bcol + bc];
    As[0][ac + 0][ar] = a0.x; As[0][ac + 1][ar] = a0.y;
    As[0][ac + 2][ar] = a0.z; As[0][ac + 3][ar] = a0.w;
    As[0][ac + 0][ar + 64] = a1.x; As[0][ac + 1][ar + 64] = a1.y;
    As[0][ac + 2][ar + 64] = a1.z; As[0][ac + 3][ar + 64] = a1.w;
    *(float4*)&Bs[0][br][bc]     = b0;
    *(float4*)&Bs[0][br + 8][bc] = b1;
    __syncthreads();

    float acc[8][8] = {};
    int ntiles = K >> 4;

    for (int t = 0; t < ntiles; t++) {
        int cur = t & 1;
        if (t + 1 < ntiles) {
            int k0 = (t + 1) << 4;
            a0 = *(const float4*)&A[(size_t)(brow + ar)      * K + k0 + ac];
            a1 = *(const float4*)&A[(size_t)(brow + ar + 64) * K + k0 + ac];
            b0 = *(const float4*)&B[(size_t)(k0 + br)     * N + bcol + bc];
            b1 = *(const float4*)&B[(size_t)(k0 + br + 8) * N + bcol + bc];
        }
#pragma unroll
        for (int k = 0; k < 16; k++) {
            float4 x0 = *(const float4*)&As[cur][k][ty * 8];
            float4 x1 = *(const float4*)&As[cur][k][ty * 8 + 4];
            float4 y0 = *(const float4*)&Bs[cur][k][tx * 8];
            float4 y1 = *(const float4*)&Bs[cur][k][tx * 8 + 4];
            float av[8] = {x0.x, x0.y, x0.z, x0.w, x1.x, x1.y, x1.z, x1.w};
            float bv[8] = {y0.x, y0.y, y0.z, y0.w, y1.x, y1.y, y1.z, y1.w};
#pragma unroll
            for (int i = 0; i < 8; i++)
#pragma unroll
                for (int j = 0; j < 8; j++)
                    acc[i][j] += av[i] * bv[j];
        }
        if (t + 1 < ntiles) {
            int nxt = cur ^ 1;
            As[nxt][ac + 0][ar] = a0.x; As[nxt][ac + 1][ar] = a0.y;
            As[nxt][ac + 2][ar] = a0.z; As[nxt][ac + 3][ar] = a0.w;
            As[nxt][ac + 0][ar + 64] = a1.x; As[nxt][ac + 1][ar + 64] = a1.y;
            As[nxt][ac + 2][ar + 64] = a1.z; As[nxt][ac + 3][ar + 64] = a1.w;
            *(float4*)&Bs[nxt][br][bc]     = b0;
            *(float4*)&Bs[nxt][br + 8][bc] = b1;
            __syncthreads();
        }
    }

#pragma unroll
    for (int i = 0; i < 8; i++) {
        size_t rowoff = (size_t)(brow + ty * 8 + i) * N + bcol + tx * 8;
        if (ACCUM) {
            float4 c0 = *(float4*)&C[rowoff];
            float4 c1 = *(float4*)&C[rowoff + 4];
            c0.x += acc[i][0]; c0.y += acc[i][1]; c0.z += acc[i][2]; c0.w += acc[i][3];
            c1.x += acc[i][4]; c1.y += acc[i][5]; c1.z += acc[i][6]; c1.w += acc[i][7];
            *(float4*)&C[rowoff]     = c0;
            *(float4*)&C[rowoff + 4] = c1;
        } else {
            *(float4*)&C[rowoff]     = make_float4(acc[i][0], acc[i][1], acc[i][2], acc[i][3]);
            *(float4*)&C[rowoff + 4] = make_float4(acc[i][4], acc[i][5], acc[i][6], acc[i][7]);
        }
    }
}

// ---------------- Flash attention: block per (b, h, 16-query tile) ------------------
// 128 threads: thread t -> (qi = t&15, dg = t>>4); owns ctx dims dg*16..dg*16+15.
__global__ __launch_bounds__(128) void flash_attn_kernel(const float* __restrict__ q,
                                                         const float* __restrict__ k,
                                                         const float* __restrict__ v,
                                                         float* __restrict__ ctx) {
    __shared__ float Qs[16][132];
    __shared__ float Ks[32][132];
    __shared__ float Vs[32][132];
    __shared__ float sc[16][33];
    __shared__ float m_s[16], l_s[16], corr_s[16];

    int tid = threadIdx.x;
    int gid = blockIdx.x;               // b*NH*64 + hh*64 + qtile
    int qtile = gid % 64;
    int hh = (gid / 64) % NH;
    int b  = gid / (64 * NH);
    int t0 = qtile * 16;
    int kvh = hh >> 1;                  // jnp.repeat semantics (rep=2)
    const float scale = 0.08838834764831845f;

    // Load Q tile (16 x 128)
    for (int i = tid; i < 16 * 32; i += 128) {
        int r = i >> 5, c = (i & 31) << 2;
        *(float4*)&Qs[r][c] =
            *(const float4*)&q[((size_t)(b * SEQ + t0 + r) * NH + hh) * HD + c];
    }
    if (tid < 16) { m_s[tid] = -1e30f; l_s[tid] = 0.f; }

    int qi = tid & 15;
    int dg = tid >> 4;
    float acc[16] = {};
    __syncthreads();

    int qmax = t0 + 15;
    for (int j0 = 0; j0 <= qmax; j0 += 32) {
        // Load K/V tiles (32 x 128 each)
        for (int i = tid; i < 32 * 32; i += 128) {
            int r = i >> 5, c = (i & 31) << 2;
            size_t base = ((size_t)(b * SEQ + j0 + r) * NKV + kvh) * HD + c;
            *(float4*)&Ks[r][c] = *(const float4*)&k[base];
            *(float4*)&Vs[r][c] = *(const float4*)&v[base];
        }
        __syncthreads();

        // Scores: thread (qi,dg) computes keys j = dg, dg+8, dg+16, dg+24
        float s4[4] = {0.f, 0.f, 0.f, 0.f};
        for (int d4 = 0; d4 < 32; d4++) {
            float4 qv = *(const float4*)&Qs[qi][d4 * 4];
#pragma unroll
            for (int jj = 0; jj < 4; jj++) {
                float4 kv = *(const float4*)&Ks[dg + (jj << 3)][d4 * 4];
                s4[jj] += qv.x * kv.x + qv.y * kv.y + qv.z * kv.z + qv.w * kv.w;
            }
        }
#pragma unroll
        for (int jj = 0; jj < 4; jj++) sc[qi][dg + (jj << 3)] = s4[jj];
        __syncthreads();

        // Softmax update (one thread per query)
        if (tid < 16) {
            int qg = t0 + tid;
            float m = m_s[tid];
            float mnew = m;
            for (int j = 0; j < 32; j++)
                if (j0 + j <= qg) mnew = fmaxf(mnew, sc[tid][j] * scale);
            float corr = expf(m - mnew);
            float l = l_s[tid] * corr;
            for (int j = 0; j < 32; j++) {
                float p = (j0 + j <= qg) ? expf(sc[tid][j] * scale - mnew) : 0.f;
                sc[tid][j] = p;
                l += p;
            }
            m_s[tid] = mnew;
            l_s[tid] = l;
            corr_s[tid] = corr;
        }
        __syncthreads();

        // Context accumulation
        float corr = corr_s[qi];
#pragma unroll
        for (int i = 0; i < 16; i++) acc[i] *= corr;
        for (int j = 0; j < 32; j++) {
            float p = sc[qi][j];
#pragma unroll
            for (int i4 = 0; i4 < 4; i4++) {
                float4 vv = *(const float4*)&Vs[j][dg * 16 + i4 * 4];
                acc[i4 * 4 + 0] += p * vv.x;
                acc[i4 * 4 + 1] += p * vv.y;
                acc[i4 * 4 + 2] += p * vv.z;
                acc[i4 * 4 + 3] += p * vv.w;
            }
        }
        __syncthreads();
    }

    float inv = 1.f / l_s[qi];
    float* o = &ctx[((size_t)(b * SEQ + t0 + qi) * NH + hh) * HD + dg * 16];
#pragma unroll
    for (int i = 0; i < 16; i++) o[i] = acc[i] * inv;
}

// ---------------- SiLU(g) * u (in place into g) ----------------
__global__ void silu_mul_kernel(float* __restrict__ g, const float* __restrict__ u, size_t n) {
    size_t i = (size_t)blockIdx.x * blockDim.x + threadIdx.x;
    if (i < n) {
        float x = g[i];
        g[i] = (x / (1.f + expf(-x))) * u[i];
    }
}

// ---------------- Host orchestration ----------------
static void launch_gemm(const float* A, const float* B, float* C,
                        int M, int N, int K, int accum) {
    dim3 grid(N / 128, M / 128);
    if (accum) sgemm128_kernel<true><<<grid, 256>>>(A, B, C, M, N, K);
    else       sgemm128_kernel<false><<<grid, 256>>>(A, B, C, M, N, K);
}

extern "C" void kernel_launch(void* const* d_in, const int* in_sizes, int n_in,
                              void* d_out, int out_size) {
    const int*   input_ids = (const int*)  d_in[0];
    const float* embed     = (const float*)d_in[1];
    const float* Wq        = (const float*)d_in[2];
    const float* Wk        = (const float*)d_in[3];
    const float* Wv        = (const float*)d_in[4];
    const float* Wo        = (const float*)d_in[5];
    const float* qn        = (const float*)d_in[6];
    const float* kn        = (const float*)d_in[7];
    const float* ln1       = (const float*)d_in[8];
    const float* ln2       = (const float*)d_in[9];
    const float* Wg        = (const float*)d_in[10];
    const float* Wu        = (const float*)d_in[11];
    const float* Wd        = (const float*)d_in[12];
    const float* norm_w    = (const float*)d_in[13];
    const float* lm_head   = (const float*)d_in[14];
    float* out = (float*)d_out;

    float *h, *x, *q, *k, *v, *ctx, *mg, *mu, *cost, *sint;
    cudaGetSymbolAddress((void**)&h,    g_h);
    cudaGetSymbolAddress((void**)&x,    g_x);
    cudaGetSymbolAddress((void**)&q,    g_q);
    cudaGetSymbolAddress((void**)&k,    g_k);
    cudaGetSymbolAddress((void**)&v,    g_v);
    cudaGetSymbolAddress((void**)&ctx,  g_ctx);
    cudaGetSymbolAddress((void**)&mg,   g_mg);
    cudaGetSymbolAddress((void**)&mu,   g_mu);
    cudaGetSymbolAddress((void**)&cost, g_cos);
    cudaGetSymbolAddress((void**)&sint, g_sin);

    // RoPE tables + embedding
    rope_table_kernel<<<SEQ, 64>>>(cost, sint);
    embed_kernel<<<TOK, 256>>>(input_ids, embed, h);

    for (int l = 0; l < LNUM; l++) {
        const float* wq = Wq + (size_t)l * H * QD;
        const float* wk = Wk + (size_t)l * H * KVD;
        const float* wv = Wv + (size_t)l * H * KVD;
        const float* wo = Wo + (size_t)l * QD * H;
        const float* wg = Wg + (size_t)l * H * IDIM;
        const float* wu = Wu + (size_t)l * H * IDIM;
        const float* wd = Wd + (size_t)l * IDIM * H;

        // ---- Attention block ----
        rmsnorm_kernel<<<TOK, 256>>>(h, ln1 + (size_t)l * H, x, H);
        launch_gemm(x, wq, q, TOK, QD,  H, 0);
        launch_gemm(x, wk, k, TOK, KVD, H, 0);
        launch_gemm(x, wv, v, TOK, KVD, H, 0);
        qk_norm_rope_kernel<<<TOK * NH,  HD>>>(q, qn + (size_t)l * HD, cost, sint, NH);
        qk_norm_rope_kernel<<<TOK * NKV, HD>>>(k, kn + (size_t)l * HD, cost, sint, NKV);
        flash_attn_kernel<<<BATCH * NH * (SEQ / 16), 128>>>(q, k, v, ctx);
        launch_gemm(ctx, wo, h, TOK, H, QD, 1);   // h += ctx @ Wo

        // ---- MLP block ----
        rmsnorm_kernel<<<TOK, 256>>>(h, ln2 + (size_t)l * H, x, H);
        launch_gemm(x, wg, mg, TOK, IDIM, H, 0);
        launch_gemm(x, wu, mu, TOK, IDIM, H, 0);
        {
            size_t n = (size_t)TOK * IDIM;
            silu_mul_kernel<<<(unsigned)((n + 255) / 256), 256>>>(mg, mu, n);
        }
        launch_gemm(mg, wd, h, TOK, H, IDIM, 1);  // h += (silu(g)*u) @ Wd
    }

    // Final norm + LM head
    rmsnorm_kernel<<<TOK, 256>>>(h, norm_w, x, H);
    launch_gemm(x, lm_head, out, TOK, VOC, H, 0);
}

// round 5
// speedup vs baseline: 10.2524x; 1.9504x over previous
#include <cuda_runtime.h>
#include <cuda_bf16.h>
#include <math.h>
#include <stdint.h>

// ---------------- Model constants ----------------
#define LNUM 8
#define H    1024
#define NH   16
#define NKV  8
#define HD   128
#define IDIM 3072
#define VOC  32000
#define BATCH 2
#define SEQ  1024
#define TOK  (BATCH*SEQ)          // 2048
#define QD   (NH*HD)              // 2048
#define KVD  (NKV*HD)             // 1024
#define EPS  1e-6f

// Per-layer transposed-weight offsets (bf16 hi/lo arrays, [N][K] layout)
#define OWQ 0
#define OWK (OWQ + QD*H)
#define OWV (OWK + KVD*H)
#define OWO (OWV + KVD*H)
#define OWG (OWO + H*QD)
#define OWU (OWG + (size_t)IDIM*H)
#define OWD (OWU + (size_t)IDIM*H)
#define PLSZ (OWD + (size_t)H*IDIM)
#define OLM  ((size_t)LNUM * PLSZ)
#define WT_TOTAL (OLM + (size_t)VOC*H)

// ---------------- Scratch (device globals; no allocation allowed) ----------------
__device__ float g_h  [(size_t)TOK * H];
__device__ float g_q  [(size_t)TOK * QD];
__device__ float g_k  [(size_t)TOK * KVD];
__device__ float g_v  [(size_t)TOK * KVD];
__device__ float g_mg [(size_t)TOK * IDIM];
__device__ float g_mu [(size_t)TOK * IDIM];
__device__ float g_cos[(size_t)SEQ * 64];
__device__ float g_sin[(size_t)SEQ * 64];
__device__ __nv_bfloat16 g_wT_hi[WT_TOTAL];
__device__ __nv_bfloat16 g_wT_lo[WT_TOTAL];
__device__ __nv_bfloat16 g_a_hi[(size_t)TOK * IDIM];
__device__ __nv_bfloat16 g_a_lo[(size_t)TOK * IDIM];

// ---------------- PTX helpers ----------------
__device__ __forceinline__ uint32_t smem_to_u32(const void* p) {
    uint32_t a;
    asm("{ .reg .u64 t; cvta.to.shared.u64 t, %1; cvt.u32.u64 %0, t; }" : "=r"(a) : "l"(p));
    return a;
}
__device__ __forceinline__ void cp16(uint32_t s, const void* g) {
    asm volatile("cp.async.cg.shared.global [%0], [%1], 16;" :: "r"(s), "l"(g));
}
__device__ __forceinline__ void ldsm4(uint32_t& r0, uint32_t& r1, uint32_t& r2, uint32_t& r3,
                                      uint32_t addr) {
    asm volatile("ldmatrix.sync.aligned.m8n8.x4.shared.b16 {%0,%1,%2,%3}, [%4];"
                 : "=r"(r0), "=r"(r1), "=r"(r2), "=r"(r3) : "r"(addr));
}
__device__ __forceinline__ void mma_bf16(float* c, const uint32_t* a, uint32_t b0, uint32_t b1) {
    asm volatile("mma.sync.aligned.m16n8k16.row.col.f32.bf16.bf16.f32 "
                 "{%0,%1,%2,%3}, {%4,%5,%6,%7}, {%8,%9}, {%0,%1,%2,%3};"
                 : "+f"(c[0]), "+f"(c[1]), "+f"(c[2]), "+f"(c[3])
                 : "r"(a[0]), "r"(a[1]), "r"(a[2]), "r"(a[3]), "r"(b0), "r"(b1));
}
#define SWZ(off) ((off) ^ (((off) >> 3) & 0x70))

// ---------------- Weight transpose + hi/lo bf16 split: W[KxN] -> T[N][K] ------------
__global__ void convT_kernel(const float* __restrict__ W,
                             __nv_bfloat16* __restrict__ Th,
                             __nv_bfloat16* __restrict__ Tl, int K, int N) {
    __shared__ float t[32][33];
    int n0 = blockIdx.x * 32, k0 = blockIdx.y * 32;
    int tx = threadIdx.x & 31, ty = threadIdx.x >> 5;
    for (int r = ty; r < 32; r += 8)
        t[r][tx] = W[(size_t)(k0 + r) * N + n0 + tx];
    __syncthreads();
    for (int r = ty; r < 32; r += 8) {
        float v = t[tx][r];
        __nv_bfloat16 hi = __float2bfloat16(v);
        size_t o = (size_t)(n0 + r) * K + k0 + tx;
        Th[o] = hi;
        Tl[o] = __float2bfloat16(v - __bfloat162float(hi));
    }
}

// ---------------- bf16x3 GEMM via mma.sync: C = A @ B^T (B stored [N][K]) -----------
// 128x128 CTA tile, 8 warps (2x4), warp tile 64x32, BK=64, cp.async double buffer.
#define STG 65536
__global__ __launch_bounds__(256) void gemm_mma_kernel(
    const __nv_bfloat16* __restrict__ Ah, const __nv_bfloat16* __restrict__ Al,
    const __nv_bfloat16* __restrict__ Bh, const __nv_bfloat16* __restrict__ Bl,
    float* __restrict__ C, int M, int N, int K, int accum) {
    extern __shared__ char smem[];
    uint32_t sb = smem_to_u32(smem);
    int tid = threadIdx.x, lane = tid & 31, wid = tid >> 5;
    int brow = blockIdx.y * 128, bcol = blockIdx.x * 128;
    int wm = wid & 1, wn = wid >> 1;

    float acc[4][4][4] = {};
    int T = K >> 6;

    // --- stage-load helper (each thread moves 4x16B per sub-tile) ---
    auto issue_loads = [&](int t, int s) {
        uint32_t st = sb + s * STG;
        int k0 = t << 6;
#pragma unroll
        for (int i = 0; i < 4; i++) {
            int idx = tid + i * 256;      // 0..1023
            int r = idx >> 3, g = idx & 7;
            uint32_t off = SWZ((uint32_t)(r * 128 + g * 16));
            size_t ga = (size_t)(brow + r) * K + k0 + g * 8;
            size_t gb = (size_t)(bcol + r) * K + k0 + g * 8;
            cp16(st + off,         Ah + ga);
            cp16(st + 16384 + off, Al + ga);
            cp16(st + 32768 + off, Bh + gb);
            cp16(st + 49152 + off, Bl + gb);
        }
        asm volatile("cp.async.commit_group;");
    };

    issue_loads(0, 0);

    uint32_t a_roff = (uint32_t)(wm * 64 + (lane & 15));
    uint32_t a_koff = (uint32_t)((lane >> 4) * 8);
    uint32_t b_noff = (uint32_t)(wn * 32 + ((lane >> 4) * 8) + (lane & 7));
    uint32_t b_koff = (uint32_t)(((lane >> 3) & 1) * 8);

    for (int t = 0; t < T; t++) {
        int s = t & 1;
        if (t + 1 < T) {
            issue_loads(t + 1, s ^ 1);
            asm volatile("cp.async.wait_group 1;");
        } else {
            asm volatile("cp.async.wait_group 0;");
        }
        __syncthreads();
        uint32_t st = sb + s * STG;
#pragma unroll
        for (int kk = 0; kk < 4; kk++) {
            uint32_t ah_[4][4], al_[4][4];
#pragma unroll
            for (int mi = 0; mi < 4; mi++) {
                uint32_t off = SWZ((a_roff + mi * 16) * 128 + (kk * 16 + a_koff) * 2);
                ldsm4(ah_[mi][0], ah_[mi][1], ah_[mi][2], ah_[mi][3], st + off);
                ldsm4(al_[mi][0], al_[mi][1], al_[mi][2], al_[mi][3], st + 16384 + off);
            }
            uint32_t bh_[2][4], bl_[2][4];
#pragma unroll
            for (int p = 0; p < 2; p++) {
                uint32_t off = SWZ((b_noff + p * 16) * 128 + (kk * 16 + b_koff) * 2);
                ldsm4(bh_[p][0], bh_[p][1], bh_[p][2], bh_[p][3], st + 32768 + off);
                ldsm4(bl_[p][0], bl_[p][1], bl_[p][2], bl_[p][3], st + 49152 + off);
            }
#pragma unroll
            for (int mi = 0; mi < 4; mi++)
#pragma unroll
                for (int ni = 0; ni < 4; ni++) {
                    int p = ni >> 1, q2 = (ni & 1) * 2;
                    mma_bf16(acc[mi][ni], ah_[mi], bh_[p][q2], bh_[p][q2 + 1]);
                    mma_bf16(acc[mi][ni], ah_[mi], bl_[p][q2], bl_[p][q2 + 1]);
                    mma_bf16(acc[mi][ni], al_[mi], bh_[p][q2], bh_[p][q2 + 1]);
                }
        }
        __syncthreads();
    }

    // --- epilogue ---
#pragma unroll
    for (int mi = 0; mi < 4; mi++)
#pragma unroll
        for (int ni = 0; ni < 4; ni++) {
            int r0 = brow + wm * 64 + mi * 16 + (lane >> 2);
            int c0 = bcol + wn * 32 + ni * 8 + 2 * (lane & 3);
            float2* p0 = (float2*)(C + (size_t)r0 * N + c0);
            float2* p1 = (float2*)(C + (size_t)(r0 + 8) * N + c0);
            float* a4 = acc[mi][ni];
            if (accum) {
                float2 v0 = *p0, v1 = *p1;
                v0.x += a4[0]; v0.y += a4[1];
                v1.x += a4[2]; v1.y += a4[3];
                *p0 = v0; *p1 = v1;
            } else {
                *p0 = make_float2(a4[0], a4[1]);
                *p1 = make_float2(a4[2], a4[3]);
            }
        }
}

// ---------------- RoPE tables ----------------
__global__ void rope_table_kernel(float* __restrict__ cost, float* __restrict__ sint) {
    int pos = blockIdx.x;
    int i   = threadIdx.x;
    float invf = (float)pow(1000000.0, -(double)i / 64.0);
    float angf = (float)pos * invf;
    double ang = (double)angf;
    cost[pos * 64 + i] = (float)cos(ang);
    sint[pos * 64 + i] = (float)sin(ang);
}

// ---------------- Embedding gather ----------------
__global__ void embed_kernel(const int* __restrict__ ids,
                             const float* __restrict__ emb,
                             float* __restrict__ out) {
    int t = blockIdx.x;
    int id = ids[t];
    const float* src = emb + (size_t)id * H;
    float* dst = out + (size_t)t * H;
    for (int i = threadIdx.x; i < H; i += blockDim.x) dst[i] = src[i];
}

// ---------------- Row RMSNorm with fused bf16 hi/lo split ----------------
__global__ void rmsnorm_split_kernel(const float* __restrict__ in,
                                     const float* __restrict__ w,
                                     __nv_bfloat16* __restrict__ oh,
                                     __nv_bfloat16* __restrict__ ol, int W) {
    __shared__ float red[256];
    int row = blockIdx.x;
    const float* x = in + (size_t)row * W;
    float s = 0.f;
    for (int i = threadIdx.x; i < W; i += 256) { float v = x[i]; s += v * v; }
    red[threadIdx.x] = s;
    __syncthreads();
    for (int st = 128; st > 0; st >>= 1) {
        if (threadIdx.x < st) red[threadIdx.x] += red[threadIdx.x + st];
        __syncthreads();
    }
    float rms = rsqrtf(red[0] / (float)W + EPS);
    for (int i = threadIdx.x; i < W; i += 256) {
        float v = x[i] * rms * w[i];
        __nv_bfloat16 hi = __float2bfloat16(v);
        size_t o = (size_t)row * W + i;
        oh[o] = hi;
        ol[o] = __float2bfloat16(v - __bfloat162float(hi));
    }
}

// ---------------- Per-head RMSNorm + RoPE ----------------
__global__ void qk_norm_rope_kernel(float* __restrict__ x,
                                    const float* __restrict__ w,
                                    const float* __restrict__ cost,
                                    const float* __restrict__ sint,
                                    int nheads) {
    __shared__ float sh[HD];
    __shared__ float red[HD];
    int t  = blockIdx.x / nheads;
    int hh = blockIdx.x % nheads;
    int pos = t % SEQ;
    float* p = x + ((size_t)t * nheads + hh) * HD;
    int d = threadIdx.x;
    float v = p[d];
    red[d] = v * v;
    __syncthreads();
    for (int st = 64; st > 0; st >>= 1) {
        if (d < st) red[d] += red[d + st];
        __syncthreads();
    }
    float rms = rsqrtf(red[0] / (float)HD + EPS);
    float xn = v * rms * w[d];
    sh[d] = xn;
    __syncthreads();
    int fi = d & 63;
    float c = cost[pos * 64 + fi];
    float s = sint[pos * 64 + fi];
    float other = (d < 64) ? -sh[d + 64] : sh[d - 64];
    p[d] = xn * c + other * s;
}

// ---------------- Flash attention: block per (b, h, 16-query tile); bf16 split out ---
__global__ __launch_bounds__(128) void flash_attn_kernel(const float* __restrict__ q,
                                                         const float* __restrict__ k,
                                                         const float* __restrict__ v,
                                                         __nv_bfloat16* __restrict__ oh,
                                                         __nv_bfloat16* __restrict__ ol) {
    __shared__ float Qs[16][132];
    __shared__ float Ks[32][132];
    __shared__ float Vs[32][132];
    __shared__ float sc[16][33];
    __shared__ float m_s[16], l_s[16], corr_s[16];

    int tid = threadIdx.x;
    int gid = blockIdx.x;
    int qtile = gid % 64;
    int hh = (gid / 64) % NH;
    int b  = gid / (64 * NH);
    int t0 = qtile * 16;
    int kvh = hh >> 1;
    const float scale = 0.08838834764831845f;

    for (int i = tid; i < 16 * 32; i += 128) {
        int r = i >> 5, c = (i & 31) << 2;
        *(float4*)&Qs[r][c] =
            *(const float4*)&q[((size_t)(b * SEQ + t0 + r) * NH + hh) * HD + c];
    }
    if (tid < 16) { m_s[tid] = -1e30f; l_s[tid] = 0.f; }

    int qi = tid & 15;
    int dg = tid >> 4;
    float acc[16] = {};
    __syncthreads();

    int qmax = t0 + 15;
    for (int j0 = 0; j0 <= qmax; j0 += 32) {
        for (int i = tid; i < 32 * 32; i += 128) {
            int r = i >> 5, c = (i & 31) << 2;
            size_t base = ((size_t)(b * SEQ + j0 + r) * NKV + kvh) * HD + c;
            *(float4*)&Ks[r][c] = *(const float4*)&k[base];
            *(float4*)&Vs[r][c] = *(const float4*)&v[base];
        }
        __syncthreads();

        float s4[4] = {0.f, 0.f, 0.f, 0.f};
        for (int d4 = 0; d4 < 32; d4++) {
            float4 qv = *(const float4*)&Qs[qi][d4 * 4];
#pragma unroll
            for (int jj = 0; jj < 4; jj++) {
                float4 kv = *(const float4*)&Ks[dg + (jj << 3)][d4 * 4];
                s4[jj] += qv.x * kv.x + qv.y * kv.y + qv.z * kv.z + qv.w * kv.w;
            }
        }
#pragma unroll
        for (int jj = 0; jj < 4; jj++) sc[qi][dg + (jj << 3)] = s4[jj];
        __syncthreads();

        if (tid < 16) {
            int qg = t0 + tid;
            float m = m_s[tid];
            float mnew = m;
            for (int j = 0; j < 32; j++)
                if (j0 + j <= qg) mnew = fmaxf(mnew, sc[tid][j] * scale);
            float corr = expf(m - mnew);
            float l = l_s[tid] * corr;
            for (int j = 0; j < 32; j++) {
                float p = (j0 + j <= qg) ? expf(sc[tid][j] * scale - mnew) : 0.f;
                sc[tid][j] = p;
                l += p;
            }
            m_s[tid] = mnew;
            l_s[tid] = l;
            corr_s[tid] = corr;
        }
        __syncthreads();

        float corr = corr_s[qi];
#pragma unroll
        for (int i = 0; i < 16; i++) acc[i] *= corr;
        for (int j = 0; j < 32; j++) {
            float p = sc[qi][j];
#pragma unroll
            for (int i4 = 0; i4 < 4; i4++) {
                float4 vv = *(const float4*)&Vs[j][dg * 16 + i4 * 4];
                acc[i4 * 4 + 0] += p * vv.x;
                acc[i4 * 4 + 1] += p * vv.y;
                acc[i4 * 4 + 2] += p * vv.z;
                acc[i4 * 4 + 3] += p * vv.w;
            }
        }
        __syncthreads();
    }

    float inv = 1.f / l_s[qi];
    size_t ob = ((size_t)(b * SEQ + t0 + qi) * NH + hh) * HD + dg * 16;
#pragma unroll
    for (int i = 0; i < 16; i++) {
        float val = acc[i] * inv;
        __nv_bfloat16 hi = __float2bfloat16(val);
        oh[ob + i] = hi;
        ol[ob + i] = __float2bfloat16(val - __bfloat162float(hi));
    }
}

// ---------------- SiLU(g) * u with fused bf16 hi/lo split ----------------
__global__ void silu_mul_split_kernel(const float* __restrict__ g,
                                      const float* __restrict__ u,
                                      __nv_bfloat16* __restrict__ oh,
                                      __nv_bfloat16* __restrict__ ol, size_t n) {
    size_t i = (size_t)blockIdx.x * blockDim.x + threadIdx.x;
    if (i < n) {
        float x = g[i];
        float val = (x / (1.f + expf(-x))) * u[i];
        __nv_bfloat16 hi = __float2bfloat16(val);
        oh[i] = hi;
        ol[i] = __float2bfloat16(val - __bfloat162float(hi));
    }
}

// ---------------- Host orchestration ----------------
#define GSM_TOTAL (2 * STG)
static void launch_gemm3(const __nv_bfloat16* Ah, const __nv_bfloat16* Al,
                         const __nv_bfloat16* Bh, const __nv_bfloat16* Bl,
                         float* C, int M, int N, int K, int accum) {
    dim3 grid(N / 128, M / 128);
    gemm_mma_kernel<<<grid, 256, GSM_TOTAL>>>(Ah, Al, Bh, Bl, C, M, N, K, accum);
}

extern "C" void kernel_launch(void* const* d_in, const int* in_sizes, int n_in,
                              void* d_out, int out_size) {
    const int*   input_ids = (const int*)  d_in[0];
    const float* embed     = (const float*)d_in[1];
    const float* Wq        = (const float*)d_in[2];
    const float* Wk        = (const float*)d_in[3];
    const float* Wv        = (const float*)d_in[4];
    const float* Wo        = (const float*)d_in[5];
    const float* qn        = (const float*)d_in[6];
    const float* kn        = (const float*)d_in[7];
    const float* ln1       = (const float*)d_in[8];
    const float* ln2       = (const float*)d_in[9];
    const float* Wg        = (const float*)d_in[10];
    const float* Wu        = (const float*)d_in[11];
    const float* Wd        = (const float*)d_in[12];
    const float* norm_w    = (const float*)d_in[13];
    const float* lm_head   = (const float*)d_in[14];
    float* out = (float*)d_out;

    float *h, *q, *k, *v, *mg, *mu, *cost, *sint;
    __nv_bfloat16 *wth, *wtl, *ah, *al;
    cudaGetSymbolAddress((void**)&h,    g_h);
    cudaGetSymbolAddress((void**)&q,    g_q);
    cudaGetSymbolAddress((void**)&k,    g_k);
    cudaGetSymbolAddress((void**)&v,    g_v);
    cudaGetSymbolAddress((void**)&mg,   g_mg);
    cudaGetSymbolAddress((void**)&mu,   g_mu);
    cudaGetSymbolAddress((void**)&cost, g_cos);
    cudaGetSymbolAddress((void**)&sint, g_sin);
    cudaGetSymbolAddress((void**)&wth,  g_wT_hi);
    cudaGetSymbolAddress((void**)&wtl,  g_wT_lo);
    cudaGetSymbolAddress((void**)&ah,   g_a_hi);
    cudaGetSymbolAddress((void**)&al,   g_a_lo);

    cudaFuncSetAttribute(gemm_mma_kernel,
                         cudaFuncAttributeMaxDynamicSharedMemorySize, GSM_TOTAL);

    // ---- Weight transpose + bf16 hi/lo split ----
    for (int l = 0; l < LNUM; l++) {
        size_t base = (size_t)l * PLSZ;
        convT_kernel<<<dim3(QD / 32,   H / 32),   256>>>(Wq + (size_t)l * H * QD,   wth + base + OWQ, wtl + base + OWQ, H,   QD);
        convT_kernel<<<dim3(KVD / 32,  H / 32),   256>>>(Wk + (size_t)l * H * KVD,  wth + base + OWK, wtl + base + OWK, H,   KVD);
        convT_kernel<<<dim3(KVD / 32,  H / 32),   256>>>(Wv + (size_t)l * H * KVD,  wth + base + OWV, wtl + base + OWV, H,   KVD);
        convT_kernel<<<dim3(H / 32,    QD / 32),  256>>>(Wo + (size_t)l * QD * H,   wth + base + OWO, wtl + base + OWO, QD,  H);
        convT_kernel<<<dim3(IDIM / 32, H / 32),   256>>>(Wg + (size_t)l * H * IDIM, wth + base + OWG, wtl + base + OWG, H,   IDIM);
        convT_kernel<<<dim3(IDIM / 32, H / 32),   256>>>(Wu + (size_t)l * H * IDIM, wth + base + OWU, wtl + base + OWU, H,   IDIM);
        convT_kernel<<<dim3(H / 32,    IDIM / 32),256>>>(Wd + (size_t)l * IDIM * H, wth + base + OWD, wtl + base + OWD, IDIM,H);
    }
    convT_kernel<<<dim3(VOC / 32, H / 32), 256>>>(lm_head, wth + OLM, wtl + OLM, H, VOC);

    // ---- RoPE tables + embedding ----
    rope_table_kernel<<<SEQ, 64>>>(cost, sint);
    embed_kernel<<<TOK, 256>>>(input_ids, embed, h);

    for (int l = 0; l < LNUM; l++) {
        size_t base = (size_t)l * PLSZ;

        // ---- Attention block ----
        rmsnorm_split_kernel<<<TOK, 256>>>(h, ln1 + (size_t)l * H, ah, al, H);
        launch_gemm3(ah, al, wth + base + OWQ, wtl + base + OWQ, q, TOK, QD,  H, 0);
        launch_gemm3(ah, al, wth + base + OWK, wtl + base + OWK, k, TOK, KVD, H, 0);
        launch_gemm3(ah, al, wth + base + OWV, wtl + base + OWV, v, TOK, KVD, H, 0);
        qk_norm_rope_kernel<<<TOK * NH,  HD>>>(q, qn + (size_t)l * HD, cost, sint, NH);
        qk_norm_rope_kernel<<<TOK * NKV, HD>>>(k, kn + (size_t)l * HD, cost, sint, NKV);
        flash_attn_kernel<<<BATCH * NH * (SEQ / 16), 128>>>(q, k, v, ah, al);
        launch_gemm3(ah, al, wth + base + OWO, wtl + base + OWO, h, TOK, H, QD, 1);

        // ---- MLP block ----
        rmsnorm_split_kernel<<<TOK, 256>>>(h, ln2 + (size_t)l * H, ah, al, H);
        launch_gemm3(ah, al, wth + base + OWG, wtl + base + OWG, mg, TOK, IDIM, H, 0);
        launch_gemm3(ah, al, wth + base + OWU, wtl + base + OWU, mu, TOK, IDIM, H, 0);
        {
            size_t n = (size_t)TOK * IDIM;
            silu_mul_split_kernel<<<(unsigned)((n + 255) / 256), 256>>>(mg, mu, ah, al, n);
        }
        launch_gemm3(ah, al, wth + base + OWD, wtl + base + OWD, h, TOK, H, IDIM, 1);
    }

    // ---- Final norm + LM head ----
    rmsnorm_split_kernel<<<TOK, 256>>>(h, norm_w, ah, al, H);
    launch_gemm3(ah, al, wth + OLM, wtl + OLM, out, TOK, VOC, H, 0);
}

// round 8
// speedup vs baseline: 16.0187x; 1.5624x over previous
#include <cuda_runtime.h>
#include <cuda_bf16.h>
#include <math.h>
#include <stdint.h>

// ---------------- Model constants ----------------
#define LNUM 8
#define H    1024
#define NH   16
#define NKV  8
#define HD   128
#define IDIM 3072
#define VOC  32000
#define BATCH 2
#define SEQ  1024
#define TOK  (BATCH*SEQ)          // 2048
#define QD   (NH*HD)              // 2048
#define KVD  (NKV*HD)             // 1024
#define EPS  1e-6f
#define ATT_SCALE 0.08838834764831845f

// Per-layer transposed-weight offsets (bf16 hi/lo arrays, [N][K] layout)
#define OWQ 0
#define OWK (OWQ + QD*H)
#define OWV (OWK + KVD*H)
#define OWO (OWV + KVD*H)
#define OWG (OWO + H*QD)
#define OWU (OWG + (size_t)IDIM*H)
#define OWD (OWU + (size_t)IDIM*H)
#define PLSZ (OWD + (size_t)H*IDIM)
#define OLM  ((size_t)LNUM * PLSZ)
#define WT_TOTAL (OLM + (size_t)VOC*H)

// ---------------- Scratch (device globals; no allocation allowed) ----------------
__device__ float g_h  [(size_t)TOK * H];
__device__ float g_q  [(size_t)TOK * QD];
__device__ float g_k  [(size_t)TOK * KVD];
__device__ float g_mg [(size_t)TOK * IDIM];
__device__ float g_mu [(size_t)TOK * IDIM];
__device__ float g_cos[(size_t)SEQ * 64];
__device__ float g_sin[(size_t)SEQ * 64];
__device__ __nv_bfloat16 g_wT_hi[WT_TOTAL];
__device__ __nv_bfloat16 g_wT_lo[WT_TOTAL];
__device__ __nv_bfloat16 g_a_hi[(size_t)TOK * IDIM];
__device__ __nv_bfloat16 g_a_lo[(size_t)TOK * IDIM];
__device__ __nv_bfloat16 g_qh[(size_t)TOK * QD];
__device__ __nv_bfloat16 g_ql[(size_t)TOK * QD];
__device__ __nv_bfloat16 g_kh[(size_t)TOK * KVD];
__device__ __nv_bfloat16 g_kl[(size_t)TOK * KVD];
__device__ __nv_bfloat16 g_vth[(size_t)TOK * KVD];   // [b][kvh][dim][seq]
__device__ __nv_bfloat16 g_vtl[(size_t)TOK * KVD];

// ---------------- PTX helpers ----------------
__device__ __forceinline__ uint32_t smem_to_u32(const void* p) {
    uint32_t a;
    asm("{ .reg .u64 t; cvta.to.shared.u64 t, %1; cvt.u32.u64 %0, t; }" : "=r"(a) : "l"(p));
    return a;
}
__device__ __forceinline__ void cp16(uint32_t s, const void* g) {
    asm volatile("cp.async.cg.shared.global [%0], [%1], 16;" :: "r"(s), "l"(g));
}
__device__ __forceinline__ void ldsm4(uint32_t* r, uint32_t addr) {
    asm volatile("ldmatrix.sync.aligned.m8n8.x4.shared.b16 {%0,%1,%2,%3}, [%4];"
                 : "=r"(r[0]), "=r"(r[1]), "=r"(r[2]), "=r"(r[3]) : "r"(addr));
}
__device__ __forceinline__ void mma_bf16(float* c, const uint32_t* a, uint32_t b0, uint32_t b1) {
    asm volatile("mma.sync.aligned.m16n8k16.row.col.f32.bf16.bf16.f32 "
                 "{%0,%1,%2,%3}, {%4,%5,%6,%7}, {%8,%9}, {%0,%1,%2,%3};"
                 : "+f"(c[0]), "+f"(c[1]), "+f"(c[2]), "+f"(c[3])
                 : "r"(a[0]), "r"(a[1]), "r"(a[2]), "r"(a[3]), "r"(b0), "r"(b1));
}
#define SWZ(off) ((off) ^ (((off) >> 3) & 0x70))

__device__ __forceinline__ uint32_t pack_bf16(float a, float b) {
    __nv_bfloat162 h;
    h.x = __float2bfloat16(a);
    h.y = __float2bfloat16(b);
    return *(uint32_t*)&h;
}

// ---------------- Weight transpose + hi/lo bf16 split: W[KxN] -> T[N][K] ------------
__global__ __launch_bounds__(256) void convT_kernel(const float* __restrict__ W,
                                                    __nv_bfloat16* __restrict__ Th,
                                                    __nv_bfloat16* __restrict__ Tl,
                                                    int K, int N) {
    __shared__ float sm[64][65];
    int n0 = blockIdx.x * 64, k0 = blockIdx.y * 64;
    int t = threadIdx.x;
    int rr = t >> 4, cc = (t & 15) * 4;
#pragma unroll
    for (int it = 0; it < 4; it++) {
        int kr = rr + it * 16;
        float4 v = *(const float4*)&W[(size_t)(k0 + kr) * N + n0 + cc];
        sm[kr][cc + 0] = v.x;  sm[kr][cc + 1] = v.y;
        sm[kr][cc + 2] = v.z;  sm[kr][cc + 3] = v.w;
    }
    __syncthreads();
#pragma unroll
    for (int it = 0; it < 4; it++) {
        int nr = rr + it * 16;
        float v0 = sm[cc + 0][nr], v1 = sm[cc + 1][nr];
        float v2 = sm[cc + 2][nr], v3 = sm[cc + 3][nr];
        __nv_bfloat16 h0 = __float2bfloat16(v0), h1 = __float2bfloat16(v1);
        __nv_bfloat16 h2 = __float2bfloat16(v2), h3 = __float2bfloat16(v3);
        uint32_t hp0 = pack_bf16(v0, v1), hp1 = pack_bf16(v2, v3);
        uint32_t lp0 = pack_bf16(v0 - __bfloat162float(h0), v1 - __bfloat162float(h1));
        uint32_t lp1 = pack_bf16(v2 - __bfloat162float(h2), v3 - __bfloat162float(h3));
        size_t o = (size_t)(n0 + nr) * K + k0 + cc;
        *(uint2*)&Th[o] = make_uint2(hp0, hp1);
        *(uint2*)&Tl[o] = make_uint2(lp0, lp1);
    }
}

// ---------------- bf16x3 GEMM via mma.sync: C = A @ B^T (B stored [N][K]) -----------
// mode 0: C = result; mode 1: C += result; mode 2: write V-transposed bf16 hi/lo.
#define STG 65536
__global__ __launch_bounds__(256) void gemm_mma_kernel(
    const __nv_bfloat16* __restrict__ Ah, const __nv_bfloat16* __restrict__ Al,
    const __nv_bfloat16* __restrict__ Bh, const __nv_bfloat16* __restrict__ Bl,
    float* __restrict__ C, __nv_bfloat16* __restrict__ Oh, __nv_bfloat16* __restrict__ Ol,
    int M, int N, int K, int mode) {
    extern __shared__ char smem[];
    uint32_t sb = smem_to_u32(smem);
    int tid = threadIdx.x, lane = tid & 31, wid = tid >> 5;
    int brow = blockIdx.y * 128, bcol = blockIdx.x * 128;
    int wm = wid & 1, wn = wid >> 1;

    float acc[4][4][4] = {};
    int T = K >> 6;

    auto issue_loads = [&](int t, int s) {
        uint32_t st = sb + s * STG;
        int k0 = t << 6;
#pragma unroll
        for (int i = 0; i < 4; i++) {
            int idx = tid + i * 256;
            int r = idx >> 3, g = idx & 7;
            uint32_t off = SWZ((uint32_t)(r * 128 + g * 16));
            size_t ga = (size_t)(brow + r) * K + k0 + g * 8;
            size_t gb = (size_t)(bcol + r) * K + k0 + g * 8;
            cp16(st + off,         Ah + ga);
            cp16(st + 16384 + off, Al + ga);
            cp16(st + 32768 + off, Bh + gb);
            cp16(st + 49152 + off, Bl + gb);
        }
        asm volatile("cp.async.commit_group;");
    };

    issue_loads(0, 0);

    uint32_t a_roff = (uint32_t)(wm * 64 + (lane & 15));
    uint32_t a_koff = (uint32_t)((lane >> 4) * 8);
    uint32_t b_noff = (uint32_t)(wn * 32 + ((lane >> 4) * 8) + (lane & 7));
    uint32_t b_koff = (uint32_t)(((lane >> 3) & 1) * 8);

    for (int t = 0; t < T; t++) {
        int s = t & 1;
        if (t + 1 < T) {
            issue_loads(t + 1, s ^ 1);
            asm volatile("cp.async.wait_group 1;");
        } else {
            asm volatile("cp.async.wait_group 0;");
        }
        __syncthreads();
        uint32_t st = sb + s * STG;
#pragma unroll
        for (int kk = 0; kk < 4; kk++) {
            uint32_t ah_[4][4], al_[4][4];
#pragma unroll
            for (int mi = 0; mi < 4; mi++) {
                uint32_t off = SWZ((a_roff + mi * 16) * 128 + (kk * 16 + a_koff) * 2);
                ldsm4(ah_[mi], st + off);
                ldsm4(al_[mi], st + 16384 + off);
            }
            uint32_t bh_[2][4], bl_[2][4];
#pragma unroll
            for (int p = 0; p < 2; p++) {
                uint32_t off = SWZ((b_noff + p * 16) * 128 + (kk * 16 + b_koff) * 2);
                ldsm4(bh_[p], st + 32768 + off);
                ldsm4(bl_[p], st + 49152 + off);
            }
#pragma unroll
            for (int mi = 0; mi < 4; mi++)
#pragma unroll
                for (int ni = 0; ni < 4; ni++) {
                    int p = ni >> 1, q2 = (ni & 1) * 2;
                    mma_bf16(acc[mi][ni], ah_[mi], bh_[p][q2], bh_[p][q2 + 1]);
                    mma_bf16(acc[mi][ni], ah_[mi], bl_[p][q2], bl_[p][q2 + 1]);
                    mma_bf16(acc[mi][ni], al_[mi], bh_[p][q2], bh_[p][q2 + 1]);
                }
        }
        __syncthreads();
    }

#pragma unroll
    for (int mi = 0; mi < 4; mi++)
#pragma unroll
        for (int ni = 0; ni < 4; ni++) {
            int r0 = brow + wm * 64 + mi * 16 + (lane >> 2);
            int c0 = bcol + wn * 32 + ni * 8 + 2 * (lane & 3);
            float* a4 = acc[mi][ni];
            if (mode == 2) {
                // V transposed split store: vt[((b*NKV+kvh)*HD+hd)*SEQ+seq]
#pragma unroll
                for (int e = 0; e < 4; e++) {
                    int r = r0 + (e >> 1) * 8;
                    int c = c0 + (e & 1);
                    int b = r >> 10, seq = r & 1023;
                    int kvh = c >> 7, hd = c & 127;
                    size_t idx = ((size_t)((b * NKV + kvh) * HD + hd)) * SEQ + seq;
                    float v = a4[e];
                    __nv_bfloat16 hi = __float2bfloat16(v);
                    Oh[idx] = hi;
                    Ol[idx] = __float2bfloat16(v - __bfloat162float(hi));
                }
            } else {
                float2* p0 = (float2*)(C + (size_t)r0 * N + c0);
                float2* p1 = (float2*)(C + (size_t)(r0 + 8) * N + c0);
                if (mode == 1) {
                    float2 v0 = *p0, v1 = *p1;
                    v0.x += a4[0]; v0.y += a4[1];
                    v1.x += a4[2]; v1.y += a4[3];
                    *p0 = v0; *p1 = v1;
                } else {
                    *p0 = make_float2(a4[0], a4[1]);
                    *p1 = make_float2(a4[2], a4[3]);
                }
            }
        }
}

// ---------------- Tensor-core flash attention ----------------
// Block: (b, h, 64-query tile). 4 warps, warp owns 16 q rows. K-tiles of 64 keys.
// smem: QH 0 | QL 16K | KH 32K | KL 48K | VH 64K | VL 80K  (96KB total)
#define ASM_BYTES 98304
__global__ __launch_bounds__(128, 2) void flash_attn_tc_kernel(
    const __nv_bfloat16* __restrict__ qh, const __nv_bfloat16* __restrict__ ql,
    const __nv_bfloat16* __restrict__ kh, const __nv_bfloat16* __restrict__ kl,
    const __nv_bfloat16* __restrict__ vth, const __nv_bfloat16* __restrict__ vtl,
    __nv_bfloat16* __restrict__ oh, __nv_bfloat16* __restrict__ ol) {
    extern __shared__ char smem[];
    uint32_t sb = smem_to_u32(smem);
    int tid = threadIdx.x, lane = tid & 31, w = tid >> 5;
    int gid = blockIdx.x;
    int qt = gid & 15, hh = (gid >> 4) & 15, b = gid >> 8;
    int t0 = qt * 64;
    int kvh = hh >> 1;

    // ---- load Q tile (hi/lo), 2 dim-chunks of 64 ----
    for (int i = tid; i < 1024; i += 128) {
        int c = i >> 9, r = (i >> 3) & 63, g = i & 7;
        uint32_t off = c * 8192 + SWZ((uint32_t)(r * 128 + g * 16));
        size_t gq = ((size_t)(b * SEQ + t0 + r) * NH + hh) * HD + c * 64 + g * 8;
        cp16(sb + off,         qh + gq);
        cp16(sb + 16384 + off, ql + gq);
    }
    asm volatile("cp.async.commit_group;");
    asm volatile("cp.async.wait_group 0;");
    __syncthreads();

    // ---- extract Q fragments ----
    uint32_t qah[2][4][4], qal[2][4][4];
#pragma unroll
    for (int c = 0; c < 2; c++)
#pragma unroll
        for (int kk = 0; kk < 4; kk++) {
            uint32_t off = c * 8192 +
                SWZ((uint32_t)((w * 16 + (lane & 15)) * 128 + (kk * 16 + (lane >> 4) * 8) * 2));
            ldsm4(qah[c][kk], sb + off);
            ldsm4(qal[c][kk], sb + 16384 + off);
        }

    float cacc[16][4] = {};
    float m0 = -1e30f, m1 = -1e30f, l0 = 0.f, l1 = 0.f;
    int r0g = t0 + w * 16 + (lane >> 2);
    int r1g = r0g + 8;

    for (int j0 = 0; j0 <= t0; j0 += 64) {
        // ---- load K + Vt tiles ----
        for (int i = tid; i < 1024; i += 128) {
            int c = i >> 9, r = (i >> 3) & 63, g = i & 7;
            uint32_t koff = c * 8192 + SWZ((uint32_t)(r * 128 + g * 16));
            size_t gk = ((size_t)(b * SEQ + j0 + r) * NKV + kvh) * HD + c * 64 + g * 8;
            cp16(sb + 32768 + koff, kh + gk);
            cp16(sb + 49152 + koff, kl + gk);
            int dim = i >> 3, g2 = i & 7;
            uint32_t voff = SWZ((uint32_t)(dim * 128 + g2 * 16));
            size_t gv = ((size_t)((b * NKV + kvh) * HD + dim)) * SEQ + j0 + g2 * 8;
            cp16(sb + 65536 + voff, vth + gv);
            cp16(sb + 81920 + voff, vtl + gv);
        }
        asm volatile("cp.async.commit_group;");
        asm volatile("cp.async.wait_group 0;");
        __syncthreads();

        // ---- S = Q K^T (bf16x3) ----
        float sacc[8][4] = {};
#pragma unroll
        for (int c = 0; c < 2; c++)
#pragma unroll
            for (int kk = 0; kk < 4; kk++) {
#pragma unroll
                for (int p = 0; p < 4; p++) {
                    uint32_t off = c * 8192 +
                        SWZ((uint32_t)((p * 16 + (lane >> 4) * 8 + (lane & 7)) * 128 +
                                       (kk * 16 + ((lane >> 3) & 1) * 8) * 2));
                    uint32_t bh4[4], bl4[4];
                    ldsm4(bh4, sb + 32768 + off);
                    ldsm4(bl4, sb + 49152 + off);
                    mma_bf16(sacc[2 * p],     qah[c][kk], bh4[0], bh4[1]);
                    mma_bf16(sacc[2 * p],     qah[c][kk], bl4[0], bl4[1]);
                    mma_bf16(sacc[2 * p],     qal[c][kk], bh4[0], bh4[1]);
                    mma_bf16(sacc[2 * p + 1], qah[c][kk], bh4[2], bh4[3]);
                    mma_bf16(sacc[2 * p + 1], qah[c][kk], bl4[2], bl4[3]);
                    mma_bf16(sacc[2 * p + 1], qal[c][kk], bh4[2], bh4[3]);
                }
            }

        // ---- causal mask (diagonal tile only) ----
        if (j0 == t0) {
#pragma unroll
            for (int ni = 0; ni < 8; ni++) {
                int colb = j0 + ni * 8 + 2 * (lane & 3);
                if (colb     > r0g) sacc[ni][0] = -1e30f;
                if (colb + 1 > r0g) sacc[ni][1] = -1e30f;
                if (colb     > r1g) sacc[ni][2] = -1e30f;
                if (colb + 1 > r1g) sacc[ni][3] = -1e30f;
            }
        }

        // ---- online softmax ----
        float rmax0 = -1e30f, rmax1 = -1e30f;
#pragma unroll
        for (int ni = 0; ni < 8; ni++) {
            rmax0 = fmaxf(rmax0, fmaxf(sacc[ni][0], sacc[ni][1]));
            rmax1 = fmaxf(rmax1, fmaxf(sacc[ni][2], sacc[ni][3]));
        }
        rmax0 = fmaxf(rmax0, __shfl_xor_sync(0xffffffffu, rmax0, 1));
        rmax0 = fmaxf(rmax0, __shfl_xor_sync(0xffffffffu, rmax0, 2));
        rmax1 = fmaxf(rmax1, __shfl_xor_sync(0xffffffffu, rmax1, 1));
        rmax1 = fmaxf(rmax1, __shfl_xor_sync(0xffffffffu, rmax1, 2));
        float mn0 = fmaxf(m0, rmax0), mn1 = fmaxf(m1, rmax1);
        float corr0 = __expf(m0 - mn0), corr1 = __expf(m1 - mn1);
        float rs0 = 0.f, rs1 = 0.f;
#pragma unroll
        for (int ni = 0; ni < 8; ni++) {
            sacc[ni][0] = __expf(sacc[ni][0] - mn0);
            sacc[ni][1] = __expf(sacc[ni][1] - mn0);
            sacc[ni][2] = __expf(sacc[ni][2] - mn1);
            sacc[ni][3] = __expf(sacc[ni][3] - mn1);
            rs0 += sacc[ni][0] + sacc[ni][1];
            rs1 += sacc[ni][2] + sacc[ni][3];
        }
        rs0 += __shfl_xor_sync(0xffffffffu, rs0, 1);
        rs0 += __shfl_xor_sync(0xffffffffu, rs0, 2);
        rs1 += __shfl_xor_sync(0xffffffffu, rs1, 1);
        rs1 += __shfl_xor_sync(0xffffffffu, rs1, 2);
        l0 = l0 * corr0 + rs0;  m0 = mn0;
        l1 = l1 * corr1 + rs1;  m1 = mn1;
#pragma unroll
        for (int n = 0; n < 16; n++) {
            cacc[n][0] *= corr0; cacc[n][1] *= corr0;
            cacc[n][2] *= corr1; cacc[n][3] *= corr1;
        }

        // ---- ctx += P V (bf16x3); P frags from S C-regs ----
#pragma unroll
        for (int kk = 0; kk < 4; kk++) {
            uint32_t pah[4], pal[4];
            float* s0 = sacc[2 * kk];
            float* s1 = sacc[2 * kk + 1];
            pah[0] = pack_bf16(s0[0], s0[1]);
            pah[1] = pack_bf16(s0[2], s0[3]);
            pah[2] = pack_bf16(s1[0], s1[1]);
            pah[3] = pack_bf16(s1[2], s1[3]);
            {
                __nv_bfloat162* h;
                h = (__nv_bfloat162*)&pah[0];
                pal[0] = pack_bf16(s0[0] - __bfloat162float(h->x), s0[1] - __bfloat162float(h->y));
                h = (__nv_bfloat162*)&pah[1];
                pal[1] = pack_bf16(s0[2] - __bfloat162float(h->x), s0[3] - __bfloat162float(h->y));
                h = (__nv_bfloat162*)&pah[2];
                pal[2] = pack_bf16(s1[0] - __bfloat162float(h->x), s1[1] - __bfloat162float(h->y));
                h = (__nv_bfloat162*)&pah[3];
                pal[3] = pack_bf16(s1[2] - __bfloat162float(h->x), s1[3] - __bfloat162float(h->y));
            }
#pragma unroll
            for (int p = 0; p < 8; p++) {
                uint32_t off = SWZ((uint32_t)((p * 16 + (lane >> 4) * 8 + (lane & 7)) * 128 +
                                              (kk * 16 + ((lane >> 3) & 1) * 8) * 2));
                uint32_t vh4[4], vl4[4];
                ldsm4(vh4, sb + 65536 + off);
                ldsm4(vl4, sb + 81920 + off);
                mma_bf16(cacc[2 * p],     pah, vh4[0], vh4[1]);
                mma_bf16(cacc[2 * p],     pah, vl4[0], vl4[1]);
                mma_bf16(cacc[2 * p],     pal, vh4[0], vh4[1]);
                mma_bf16(cacc[2 * p + 1], pah, vh4[2], vh4[3]);
                mma_bf16(cacc[2 * p + 1], pah, vl4[2], vl4[3]);
                mma_bf16(cacc[2 * p + 1], pal, vh4[2], vh4[3]);
            }
        }
        __syncthreads();
    }

    // ---- epilogue: normalize, split, store ----
    float inv0 = 1.f / l0, inv1 = 1.f / l1;
    size_t tok0 = (size_t)(b * SEQ) + t0 + w * 16 + (lane >> 2);
    size_t tok1 = tok0 + 8;
#pragma unroll
    for (int n = 0; n < 16; n++) {
        int col = hh * HD + n * 8 + 2 * (lane & 3);
        float v0 = cacc[n][0] * inv0, v1 = cacc[n][1] * inv0;
        float v2 = cacc[n][2] * inv1, v3 = cacc[n][3] * inv1;
        uint32_t h0 = pack_bf16(v0, v1);
        uint32_t h1 = pack_bf16(v2, v3);
        __nv_bfloat162* hp;
        hp = (__nv_bfloat162*)&h0;
        uint32_t lo0 = pack_bf16(v0 - __bfloat162float(hp->x), v1 - __bfloat162float(hp->y));
        hp = (__nv_bfloat162*)&h1;
        uint32_t lo1 = pack_bf16(v2 - __bfloat162float(hp->x), v3 - __bfloat162float(hp->y));
        *(uint32_t*)&oh[tok0 * QD + col] = h0;
        *(uint32_t*)&ol[tok0 * QD + col] = lo0;
        *(uint32_t*)&oh[tok1 * QD + col] = h1;
        *(uint32_t*)&ol[tok1 * QD + col] = lo1;
    }
}

// ---------------- RoPE tables ----------------
__global__ void rope_table_kernel(float* __restrict__ cost, float* __restrict__ sint) {
    int pos = blockIdx.x;
    int i   = threadIdx.x;
    float invf = (float)pow(1000000.0, -(double)i / 64.0);
    float angf = (float)pos * invf;
    double ang = (double)angf;
    cost[pos * 64 + i] = (float)cos(ang);
    sint[pos * 64 + i] = (float)sin(ang);
}

// ---------------- Embedding gather ----------------
__global__ void embed_kernel(const int* __restrict__ ids,
                             const float* __restrict__ emb,
                             float* __restrict__ out) {
    int t = blockIdx.x;
    int id = ids[t];
    const float* src = emb + (size_t)id * H;
    float* dst = out + (size_t)t * H;
    for (int i = threadIdx.x; i < H; i += blockDim.x) dst[i] = src[i];
}

// ---------------- Row RMSNorm with fused bf16 hi/lo split ----------------
__global__ void rmsnorm_split_kernel(const float* __restrict__ in,
                                     const float* __restrict__ w,
                                     __nv_bfloat16* __restrict__ oh,
                                     __nv_bfloat16* __restrict__ ol, int W) {
    __shared__ float red[256];
    int row = blockIdx.x;
    const float* x = in + (size_t)row * W;
    float s = 0.f;
    for (int i = threadIdx.x; i < W; i += 256) { float v = x[i]; s += v * v; }
    red[threadIdx.x] = s;
    __syncthreads();
    for (int st = 128; st > 0; st >>= 1) {
        if (threadIdx.x < st) red[threadIdx.x] += red[threadIdx.x + st];
        __syncthreads();
    }
    float rms = rsqrtf(red[0] / (float)W + EPS);
    for (int i = threadIdx.x; i < W; i += 256) {
        float v = x[i] * rms * w[i];
        __nv_bfloat16 hi = __float2bfloat16(v);
        size_t o = (size_t)row * W + i;
        oh[o] = hi;
        ol[o] = __float2bfloat16(v - __bfloat162float(hi));
    }
}

// ---------------- Per-head RMSNorm + RoPE + bf16 hi/lo split ----------------
__global__ void qk_norm_rope_split_kernel(const float* __restrict__ x,
                                          const float* __restrict__ w,
                                          const float* __restrict__ cost,
                                          const float* __restrict__ sint,
                                          __nv_bfloat16* __restrict__ oh,
                                          __nv_bfloat16* __restrict__ ol,
                                          int nheads, float scale) {
    __shared__ float sh[HD];
    __shared__ float red[HD];
    int t  = blockIdx.x / nheads;
    int hh = blockIdx.x % nheads;
    int pos = t % SEQ;
    const float* p = x + ((size_t)t * nheads + hh) * HD;
    int d = threadIdx.x;
    float v = p[d];
    red[d] = v * v;
    __syncthreads();
    for (int st = 64; st > 0; st >>= 1) {
        if (d < st) red[d] += red[d + st];
        __syncthreads();
    }
    float rms = rsqrtf(red[0] / (float)HD + EPS);
    float xn = v * rms * w[d];
    sh[d] = xn;
    __syncthreads();
    int fi = d & 63;
    float c = cost[pos * 64 + fi];
    float s = sint[pos * 64 + fi];
    float other = (d < 64) ? -sh[d + 64] : sh[d - 64];
    float val = (xn * c + other * s) * scale;
    __nv_bfloat16 hi = __float2bfloat16(val);
    size_t o = ((size_t)t * nheads + hh) * HD + d;
    oh[o] = hi;
    ol[o] = __float2bfloat16(val - __bfloat162float(hi));
}

// ---------------- SiLU(g) * u with fused bf16 hi/lo split ----------------
__global__ void silu_mul_split_kernel(const float* __restrict__ g,
                                      const float* __restrict__ u,
                                      __nv_bfloat16* __restrict__ oh,
                                      __nv_bfloat16* __restrict__ ol, size_t n) {
    size_t i = (size_t)blockIdx.x * blockDim.x + threadIdx.x;
    if (i < n) {
        float x = g[i];
        float val = (x / (1.f + __expf(-x))) * u[i];
        __nv_bfloat16 hi = __float2bfloat16(val);
        oh[i] = hi;
        ol[i] = __float2bfloat16(val - __bfloat162float(hi));
    }
}

// ---------------- Host orchestration ----------------
#define GSM_TOTAL (2 * STG)
static void launch_gemm3(const __nv_bfloat16* Ah, const __nv_bfloat16* Al,
                         const __nv_bfloat16* Bh, const __nv_bfloat16* Bl,
                         float* C, __nv_bfloat16* Oh, __nv_bfloat16* Ol,
                         int M, int N, int K, int mode) {
    dim3 grid(N / 128, M / 128);
    gemm_mma_kernel<<<grid, 256, GSM_TOTAL>>>(Ah, Al, Bh, Bl, C, Oh, Ol, M, N, K, mode);
}

extern "C" void kernel_launch(void* const* d_in, const int* in_sizes, int n_in,
                              void* d_out, int out_size) {
    const int*   input_ids = (const int*)  d_in[0];
    const float* embed     = (const float*)d_in[1];
    const float* Wq        = (const float*)d_in[2];
    const float* Wk        = (const float*)d_in[3];
    const float* Wv        = (const float*)d_in[4];
    const float* Wo        = (const float*)d_in[5];
    const float* qn        = (const float*)d_in[6];
    const float* kn        = (const float*)d_in[7];
    const float* ln1       = (const float*)d_in[8];
    const float* ln2       = (const float*)d_in[9];
    const float* Wg        = (const float*)d_in[10];
    const float* Wu        = (const float*)d_in[11];
    const float* Wd        = (const float*)d_in[12];
    const float* norm_w    = (const float*)d_in[13];
    const float* lm_head   = (const float*)d_in[14];
    float* out = (float*)d_out;

    float *h, *q, *k, *mg, *mu, *cost, *sint;
    __nv_bfloat16 *wth, *wtl, *ah, *al, *qh, *ql, *kh, *kl, *vth, *vtl;
    cudaGetSymbolAddress((void**)&h,    g_h);
    cudaGetSymbolAddress((void**)&q,    g_q);
    cudaGetSymbolAddress((void**)&k,    g_k);
    cudaGetSymbolAddress((void**)&mg,   g_mg);
    cudaGetSymbolAddress((void**)&mu,   g_mu);
    cudaGetSymbolAddress((void**)&cost, g_cos);
    cudaGetSymbolAddress((void**)&sint, g_sin);
    cudaGetSymbolAddress((void**)&wth,  g_wT_hi);
    cudaGetSymbolAddress((void**)&wtl,  g_wT_lo);
    cudaGetSymbolAddress((void**)&ah,   g_a_hi);
    cudaGetSymbolAddress((void**)&al,   g_a_lo);
    cudaGetSymbolAddress((void**)&qh,   g_qh);
    cudaGetSymbolAddress((void**)&ql,   g_ql);
    cudaGetSymbolAddress((void**)&kh,   g_kh);
    cudaGetSymbolAddress((void**)&kl,   g_kl);
    cudaGetSymbolAddress((void**)&vth,  g_vth);
    cudaGetSymbolAddress((void**)&vtl,  g_vtl);

    cudaFuncSetAttribute(gemm_mma_kernel,
                         cudaFuncAttributeMaxDynamicSharedMemorySize, GSM_TOTAL);
    cudaFuncSetAttribute(flash_attn_tc_kernel,
                         cudaFuncAttributeMaxDynamicSharedMemorySize, ASM_BYTES);

    // ---- Weight transpose + bf16 hi/lo split ----
    for (int l = 0; l < LNUM; l++) {
        size_t base = (size_t)l * PLSZ;
        convT_kernel<<<dim3(QD / 64,   H / 64),   256>>>(Wq + (size_t)l * H * QD,   wth + base + OWQ, wtl + base + OWQ, H,   QD);
        convT_kernel<<<dim3(KVD / 64,  H / 64),   256>>>(Wk + (size_t)l * H * KVD,  wth + base + OWK, wtl + base + OWK, H,   KVD);
        convT_kernel<<<dim3(KVD / 64,  H / 64),   256>>>(Wv + (size_t)l * H * KVD,  wth + base + OWV, wtl + base + OWV, H,   KVD);
        convT_kernel<<<dim3(H / 64,    QD / 64),  256>>>(Wo + (size_t)l * QD * H,   wth + base + OWO, wtl + base + OWO, QD,  H);
        convT_kernel<<<dim3(IDIM / 64, H / 64),   256>>>(Wg + (size_t)l * H * IDIM, wth + base + OWG, wtl + base + OWG, H,   IDIM);
        convT_kernel<<<dim3(IDIM / 64, H / 64),   256>>>(Wu + (size_t)l * H * IDIM, wth + base + OWU, wtl + base + OWU, H,   IDIM);
        convT_kernel<<<dim3(H / 64,    IDIM / 64),256>>>(Wd + (size_t)l * IDIM * H, wth + base + OWD, wtl + base + OWD, IDIM,H);
    }
    convT_kernel<<<dim3(VOC / 64, H / 64), 256>>>(lm_head, wth + OLM, wtl + OLM, H, VOC);

    // ---- RoPE tables + embedding ----
    rope_table_kernel<<<SEQ, 64>>>(cost, sint);
    embed_kernel<<<TOK, 256>>>(input_ids, embed, h);

    for (int l = 0; l < LNUM; l++) {
        size_t base = (size_t)l * PLSZ;

        // ---- Attention block ----
        rmsnorm_split_kernel<<<TOK, 256>>>(h, ln1 + (size_t)l * H, ah, al, H);
        launch_gemm3(ah, al, wth + base + OWQ, wtl + base + OWQ, q, 0, 0, TOK, QD,  H, 0);
        launch_gemm3(ah, al, wth + base + OWK, wtl + base + OWK, k, 0, 0, TOK, KVD, H, 0);
        launch_gemm3(ah, al, wth + base + OWV, wtl + base + OWV, 0, vth, vtl, TOK, KVD, H, 2);
        qk_norm_rope_split_kernel<<<TOK * NH,  HD>>>(q, qn + (size_t)l * HD, cost, sint, qh, ql, NH,  ATT_SCALE);
        qk_norm_rope_split_kernel<<<TOK * NKV, HD>>>(k, kn + (size_t)l * HD, cost, sint, kh, kl, NKV, 1.0f);
        flash_attn_tc_kernel<<<BATCH * NH * (SEQ / 64), 128, ASM_BYTES>>>(qh, ql, kh, kl, vth, vtl, ah, al);
        launch_gemm3(ah, al, wth + base + OWO, wtl + base + OWO, h, 0, 0, TOK, H, QD, 1);

        // ---- MLP block ----
        rmsnorm_split_kernel<<<TOK, 256>>>(h, ln2 + (size_t)l * H, ah, al, H);
        launch_gemm3(ah, al, wth + base + OWG, wtl + base + OWG, mg, 0, 0, TOK, IDIM, H, 0);
        launch_gemm3(ah, al, wth + base + OWU, wtl + base + OWU, mu, 0, 0, TOK, IDIM, H, 0);
        {
            size_t n = (size_t)TOK * IDIM;
            silu_mul_split_kernel<<<(unsigned)((n + 255) / 256), 256>>>(mg, mu, ah, al, n);
        }
        launch_gemm3(ah, al, wth + base + OWD, wtl + base + OWD, h, 0, 0, TOK, H, IDIM, 1);
    }

    // ---- Final norm + LM head ----
    rmsnorm_split_kernel<<<TOK, 256>>>(h, norm_w, ah, al, H);
    launch_gemm3(ah, al, wth + OLM, wtl + OLM, out, 0, 0, TOK, VOC, H, 0);
}